// round 1
// baseline (speedup 1.0000x reference)
#include <cuda_runtime.h>
#include <math.h>

#define NN 4096
#define DD 1024
#define HH 4096

// ---------------- scratch (no allocations allowed) ----------------
__device__ float g_q[(size_t)NN * HH];   // q, later reused as scores@v
__device__ float g_k[(size_t)NN * HH];   // k, later reused as ff1
__device__ float g_v[(size_t)NN * HH];   // v
__device__ float g_s[(size_t)NN * NN];   // scores
__device__ float g_t[(size_t)NN * DD];   // attn proj / ff2
__device__ float g_h[(size_t)NN * DD];   // h after first LN

// ---------------- SGEMM: C[M,N] = A[M,K] @ B  (B is [K,N] or, NT, [N,K]) ---
// 128x128x16 tile, 256 threads, 8x8 per-thread microtile.
template<bool NT, bool BIAS, bool RELU>
__global__ __launch_bounds__(256) void sgemm(const float* __restrict__ A,
                                             const float* __restrict__ B,
                                             const float* __restrict__ bias,
                                             float* __restrict__ C,
                                             int M, int N, int K) {
    __shared__ float As[16][132];
    __shared__ float Bs[16][132];
    const int bm = blockIdx.y * 128;
    const int bn = blockIdx.x * 128;
    const int tid = threadIdx.x;
    const int tx = tid & 15;        // 0..15, column group
    const int ty = tid >> 4;        // 0..15, row group

    float acc[8][8];
#pragma unroll
    for (int i = 0; i < 8; i++)
#pragma unroll
        for (int j = 0; j < 8; j++) acc[i][j] = 0.0f;

    for (int k0 = 0; k0 < K; k0 += 16) {
        // --- load A tile (128 rows x 16 k), store transposed: As[k][m] ---
#pragma unroll
        for (int l = 0; l < 2; l++) {
            int f = tid + l * 256;          // float4 index in [0,512)
            int row = f >> 2;               // 0..127
            int c4 = (f & 3) * 4;           // 0,4,8,12
            float4 va = *(const float4*)(A + (size_t)(bm + row) * K + k0 + c4);
            As[c4 + 0][row] = va.x;
            As[c4 + 1][row] = va.y;
            As[c4 + 2][row] = va.z;
            As[c4 + 3][row] = va.w;
        }
        if (NT) {
            // B is [N,K] row-major; tile rows = output cols. Store Bs[k][n].
#pragma unroll
            for (int l = 0; l < 2; l++) {
                int f = tid + l * 256;
                int row = f >> 2;           // 0..127 (n within tile)
                int c4 = (f & 3) * 4;
                float4 vb = *(const float4*)(B + (size_t)(bn + row) * K + k0 + c4);
                Bs[c4 + 0][row] = vb.x;
                Bs[c4 + 1][row] = vb.y;
                Bs[c4 + 2][row] = vb.z;
                Bs[c4 + 3][row] = vb.w;
            }
        } else {
            // B is [K,N] row-major; contiguous along n. Store Bs[k][n] direct.
#pragma unroll
            for (int l = 0; l < 2; l++) {
                int f = tid + l * 256;
                int row = f >> 5;           // 0..15 (k within tile)
                int c4 = (f & 31) * 4;      // 0..124
                float4 vb = *(const float4*)(B + (size_t)(k0 + row) * N + bn + c4);
                *(float4*)(&Bs[row][c4]) = vb;
            }
        }
        __syncthreads();

#pragma unroll
        for (int kk = 0; kk < 16; kk++) {
            float a[8], b[8];
#pragma unroll
            for (int i = 0; i < 8; i++) a[i] = As[kk][ty * 8 + i];
#pragma unroll
            for (int j = 0; j < 8; j++) b[j] = Bs[kk][tx * 8 + j];
#pragma unroll
            for (int i = 0; i < 8; i++)
#pragma unroll
                for (int j = 0; j < 8; j++) acc[i][j] += a[i] * b[j];
        }
        __syncthreads();
    }

#pragma unroll
    for (int i = 0; i < 8; i++) {
        int r = bm + ty * 8 + i;
#pragma unroll
        for (int j = 0; j < 8; j++) {
            int c = bn + tx * 8 + j;
            float val = acc[i][j];
            if (BIAS) val += bias[c];
            if (RELU) val = fmaxf(val, 0.0f);
            C[(size_t)r * N + c] = val;
        }
    }
}

// ---------------- block reduction helpers ----------------
__device__ __forceinline__ float block_reduce_max(float v) {
    __shared__ float sh[32];
    int lane = threadIdx.x & 31, w = threadIdx.x >> 5;
#pragma unroll
    for (int o = 16; o > 0; o >>= 1) v = fmaxf(v, __shfl_xor_sync(0xffffffffu, v, o));
    if (lane == 0) sh[w] = v;
    __syncthreads();
    if (threadIdx.x < 32) {
        float t = (lane < (int)(blockDim.x >> 5)) ? sh[lane] : -INFINITY;
#pragma unroll
        for (int o = 16; o > 0; o >>= 1) t = fmaxf(t, __shfl_xor_sync(0xffffffffu, t, o));
        if (lane == 0) sh[0] = t;
    }
    __syncthreads();
    float r = sh[0];
    __syncthreads();
    return r;
}

__device__ __forceinline__ float2 block_reduce_sum2(float a, float b) {
    __shared__ float sha[32], shb[32];
    int lane = threadIdx.x & 31, w = threadIdx.x >> 5;
#pragma unroll
    for (int o = 16; o > 0; o >>= 1) {
        a += __shfl_xor_sync(0xffffffffu, a, o);
        b += __shfl_xor_sync(0xffffffffu, b, o);
    }
    if (lane == 0) { sha[w] = a; shb[w] = b; }
    __syncthreads();
    if (threadIdx.x < 32) {
        int nw = (int)(blockDim.x >> 5);
        float ta = (lane < nw) ? sha[lane] : 0.0f;
        float tb = (lane < nw) ? shb[lane] : 0.0f;
#pragma unroll
        for (int o = 16; o > 0; o >>= 1) {
            ta += __shfl_xor_sync(0xffffffffu, ta, o);
            tb += __shfl_xor_sync(0xffffffffu, tb, o);
        }
        if (lane == 0) { sha[0] = ta; shb[0] = tb; }
    }
    __syncthreads();
    float2 r = make_float2(sha[0], shb[0]);
    __syncthreads();
    return r;
}

// ---------------- softmax over rows of length NN (in place) ----------------
__global__ __launch_bounds__(256) void softmax_rows(float* __restrict__ S) {
    const int row = blockIdx.x;
    float* p = S + (size_t)row * NN;
    const int tid = threadIdx.x;
    const int PER = NN / 256;   // 16
    float vals[PER];
    float mx = -INFINITY;
#pragma unroll
    for (int i = 0; i < PER; i++) {
        vals[i] = p[tid + i * 256];
        mx = fmaxf(mx, vals[i]);
    }
    mx = block_reduce_max(mx);
    float s = 0.0f;
#pragma unroll
    for (int i = 0; i < PER; i++) {
        vals[i] = __expf(vals[i] - mx);
        s += vals[i];
    }
    float2 r = block_reduce_sum2(s, 0.0f);
    float inv = 1.0f / r.x;
#pragma unroll
    for (int i = 0; i < PER; i++) p[tid + i * 256] = vals[i] * inv;
}

// ---------------- out = LayerNorm(x + res) * g + b  (rows of DD) ----------
__global__ __launch_bounds__(256) void add_layernorm(const float* __restrict__ x,
                                                     const float* __restrict__ res,
                                                     const float* __restrict__ gamma,
                                                     const float* __restrict__ beta,
                                                     float* __restrict__ out) {
    const int row = blockIdx.x;
    const int tid = threadIdx.x;
    const int PER = DD / 256;   // 4
    float vals[PER];
    float s = 0.0f, s2 = 0.0f;
#pragma unroll
    for (int i = 0; i < PER; i++) {
        int c = tid + i * 256;
        float v = x[(size_t)row * DD + c] + res[(size_t)row * DD + c];
        vals[i] = v;
        s += v;
        s2 += v * v;
    }
    float2 r = block_reduce_sum2(s, s2);
    float mu = r.x * (1.0f / DD);
    float var = r.y * (1.0f / DD) - mu * mu;
    float rstd = rsqrtf(var + 1e-5f);
#pragma unroll
    for (int i = 0; i < PER; i++) {
        int c = tid + i * 256;
        out[(size_t)row * DD + c] = (vals[i] - mu) * rstd * gamma[c] + beta[c];
    }
}

// ---------------- launch ----------------
extern "C" void kernel_launch(void* const* d_in, const int* in_sizes, int n_in,
                              void* d_out, int out_size) {
    const float* x   = (const float*)d_in[0];
    const float* Wq  = (const float*)d_in[1];
    const float* Wk  = (const float*)d_in[2];
    const float* Wv  = (const float*)d_in[3];
    const float* Wo  = (const float*)d_in[4];
    const float* W1  = (const float*)d_in[5];
    const float* b1  = (const float*)d_in[6];
    const float* W2  = (const float*)d_in[7];
    const float* b2  = (const float*)d_in[8];
    const float* g1  = (const float*)d_in[9];
    const float* be1 = (const float*)d_in[10];
    const float* g2  = (const float*)d_in[11];
    const float* be2 = (const float*)d_in[12];
    float* out = (float*)d_out;

    float *q, *k, *v, *s, *t, *h;
    cudaGetSymbolAddress((void**)&q, g_q);
    cudaGetSymbolAddress((void**)&k, g_k);
    cudaGetSymbolAddress((void**)&v, g_v);
    cudaGetSymbolAddress((void**)&s, g_s);
    cudaGetSymbolAddress((void**)&t, g_t);
    cudaGetSymbolAddress((void**)&h, g_h);
    float* av  = q;   // reuse q for scores@v
    float* ff1 = k;   // reuse k for relu(h@W1+b1)

    dim3 blk(256);
    dim3 grid_NH(HH / 128, NN / 128);   // 32 x 32
    dim3 grid_NNg(NN / 128, NN / 128);  // 32 x 32
    dim3 grid_ND(DD / 128, NN / 128);   // 8 x 32

    // q, k, v projections: [N,D]@[D,H]
    sgemm<false, false, false><<<grid_NH, blk>>>(x, Wq, nullptr, q, NN, HH, DD);
    sgemm<false, false, false><<<grid_NH, blk>>>(x, Wk, nullptr, k, NN, HH, DD);
    sgemm<false, false, false><<<grid_NH, blk>>>(x, Wv, nullptr, v, NN, HH, DD);

    // scores = q @ k^T : [N,H]@[N,H]^T
    sgemm<true, false, false><<<grid_NNg, blk>>>(q, k, nullptr, s, NN, NN, HH);
    softmax_rows<<<NN, blk>>>(s);

    // av = scores @ v : [N,N]@[N,H]
    sgemm<false, false, false><<<grid_NH, blk>>>(s, v, nullptr, av, NN, HH, NN);

    // attn = av @ Wo : [N,H]@[H,D]
    sgemm<false, false, false><<<grid_ND, blk>>>(av, Wo, nullptr, t, NN, DD, HH);

    // h = LN(x + attn)
    add_layernorm<<<NN, blk>>>(x, t, g1, be1, h);

    // ff1 = relu(h @ W1 + b1) : [N,D]@[D,H]
    sgemm<false, true, true><<<grid_NH, blk>>>(h, W1, b1, ff1, NN, HH, DD);

    // ff2 = ff1 @ W2 + b2 : [N,H]@[H,D]
    sgemm<false, true, false><<<grid_ND, blk>>>(ff1, W2, b2, t, NN, DD, HH);

    // out = LN(h + ff2)
    add_layernorm<<<NN, blk>>>(h, t, g2, be2, out);
}

// round 2
// speedup vs baseline: 3.0782x; 3.0782x over previous
#include <cuda_runtime.h>
#include <math.h>
#include <stdint.h>

#define NN 4096
#define DD 1024
#define HH 4096

// ---------------- scratch (no allocations allowed) ----------------
__device__ float g_q[(size_t)NN * HH];   // q, later reused as scores@v
__device__ float g_k[(size_t)NN * HH];   // k, later reused as ff1
__device__ float g_v[(size_t)NN * HH];   // v
__device__ float g_s[(size_t)NN * NN];   // scores
__device__ float g_t[(size_t)NN * DD];   // attn proj / ff2
__device__ float g_h[(size_t)NN * DD];   // h after first LN

__device__ __forceinline__ uint32_t f2tf32(float x) {
    uint32_t r;
    asm("cvt.rna.tf32.f32 %0, %1;" : "=r"(r) : "f"(x));
    return r;
}

__device__ __forceinline__ void mma_tf32(float* c, const uint32_t* a, uint32_t b0, uint32_t b1) {
    asm volatile(
        "mma.sync.aligned.m16n8k8.row.col.f32.tf32.tf32.f32 "
        "{%0,%1,%2,%3}, {%4,%5,%6,%7}, {%8,%9}, {%0,%1,%2,%3};"
        : "+f"(c[0]), "+f"(c[1]), "+f"(c[2]), "+f"(c[3])
        : "r"(a[0]), "r"(a[1]), "r"(a[2]), "r"(a[3]), "r"(b0), "r"(b1));
}

// ---------------- TF32 tensor-core GEMM -----------------------------------
// C[M,N] = A[M,K] @ B, where B is [K,N] (NT=false) or [N,K] (NT=true).
// Block tile 128x128x32, 256 threads = 8 warps in 4(M) x 2(N).
// Warp tile 32x64 via m16n8k8: 2 m-subtiles x 8 n-subtiles.
template<bool NT, bool BIAS, bool RELU>
__global__ __launch_bounds__(256, 2) void tgemm(const float* __restrict__ A,
                                                const float* __restrict__ B,
                                                const float* __restrict__ bias,
                                                float* __restrict__ C,
                                                int M, int N, int K) {
    // A tile: m-major, stride 36  (frag load bank = 4g+t : conflict-free)
    __shared__ uint32_t As[128 * 36];
    // B tile: NT -> n-major stride 36 ; else k-major stride 136 (bank = 8t+g)
    constexpr int BSIZE = NT ? (128 * 36) : (32 * 136);
    __shared__ uint32_t Bs[BSIZE];

    const int bm = blockIdx.y * 128;
    const int bn = blockIdx.x * 128;
    const int tid = threadIdx.x;
    const int lane = tid & 31;
    const int g = lane >> 2;     // 0..7
    const int t = lane & 3;      // 0..3
    const int warp = tid >> 5;
    const int wm = warp >> 1;    // 0..3
    const int wn = warp & 1;     // 0..1

    float acc[2][8][4];
#pragma unroll
    for (int mi = 0; mi < 2; mi++)
#pragma unroll
        for (int nj = 0; nj < 8; nj++)
#pragma unroll
            for (int e = 0; e < 4; e++) acc[mi][nj][e] = 0.0f;

    const int nchunks = K / 32;
    float4 ra[4], rb[4];

    // ---- prefetch chunk 0 into registers ----
#pragma unroll
    for (int l = 0; l < 4; l++) {
        int f = tid + l * 256;
        { // A: 128 rows x 32 k
            int row = f >> 3;
            int c4 = (f & 7) * 4;
            ra[l] = *(const float4*)(A + (size_t)(bm + row) * K + c4);
        }
        if (NT) {
            int row = f >> 3;            // n index
            int c4 = (f & 7) * 4;        // k
            rb[l] = *(const float4*)(B + (size_t)(bn + row) * K + c4);
        } else {
            int row = f >> 5;            // k index
            int c4 = (f & 31) * 4;       // n
            rb[l] = *(const float4*)(B + (size_t)row * N + bn + c4);
        }
    }

    for (int c = 0; c < nchunks; c++) {
        // ---- store regs -> smem (tf32 convert) ----
#pragma unroll
        for (int l = 0; l < 4; l++) {
            int f = tid + l * 256;
            {
                int row = f >> 3;
                int c4 = (f & 7) * 4;
                uint4 st = make_uint4(f2tf32(ra[l].x), f2tf32(ra[l].y),
                                      f2tf32(ra[l].z), f2tf32(ra[l].w));
                *(uint4*)&As[row * 36 + c4] = st;
            }
            if (NT) {
                int row = f >> 3;
                int c4 = (f & 7) * 4;
                uint4 st = make_uint4(f2tf32(rb[l].x), f2tf32(rb[l].y),
                                      f2tf32(rb[l].z), f2tf32(rb[l].w));
                *(uint4*)&Bs[row * 36 + c4] = st;
            } else {
                int row = f >> 5;
                int c4 = (f & 31) * 4;
                uint4 st = make_uint4(f2tf32(rb[l].x), f2tf32(rb[l].y),
                                      f2tf32(rb[l].z), f2tf32(rb[l].w));
                *(uint4*)&Bs[row * 136 + c4] = st;
            }
        }
        __syncthreads();

        // ---- prefetch next chunk (overlaps with mma below) ----
        if (c + 1 < nchunks) {
            int k0 = (c + 1) * 32;
#pragma unroll
            for (int l = 0; l < 4; l++) {
                int f = tid + l * 256;
                {
                    int row = f >> 3;
                    int c4 = (f & 7) * 4;
                    ra[l] = *(const float4*)(A + (size_t)(bm + row) * K + k0 + c4);
                }
                if (NT) {
                    int row = f >> 3;
                    int c4 = (f & 7) * 4;
                    rb[l] = *(const float4*)(B + (size_t)(bn + row) * K + k0 + c4);
                } else {
                    int row = f >> 5;
                    int c4 = (f & 31) * 4;
                    rb[l] = *(const float4*)(B + (size_t)(k0 + row) * N + bn + c4);
                }
            }
        }

        // ---- compute 4 k-steps of 8 ----
#pragma unroll
        for (int ks = 0; ks < 4; ks++) {
            const int kt = ks * 8 + t;
            uint32_t a[2][4];
#pragma unroll
            for (int mi = 0; mi < 2; mi++) {
                int m = wm * 32 + mi * 16 + g;
                a[mi][0] = As[m * 36 + kt];
                a[mi][1] = As[(m + 8) * 36 + kt];
                a[mi][2] = As[m * 36 + kt + 4];
                a[mi][3] = As[(m + 8) * 36 + kt + 4];
            }
#pragma unroll
            for (int nj = 0; nj < 8; nj++) {
                int n = wn * 64 + nj * 8 + g;
                uint32_t b0, b1;
                if (NT) {
                    b0 = Bs[n * 36 + kt];
                    b1 = Bs[n * 36 + kt + 4];
                } else {
                    b0 = Bs[kt * 136 + n];
                    b1 = Bs[(kt + 4) * 136 + n];
                }
                mma_tf32(acc[0][nj], a[0], b0, b1);
                mma_tf32(acc[1][nj], a[1], b0, b1);
            }
        }
        __syncthreads();
    }

    // ---- epilogue ----
#pragma unroll
    for (int mi = 0; mi < 2; mi++) {
        int row0 = bm + wm * 32 + mi * 16 + g;
        int row1 = row0 + 8;
#pragma unroll
        for (int nj = 0; nj < 8; nj++) {
            int col = bn + wn * 64 + nj * 8 + 2 * t;
            float v0 = acc[mi][nj][0], v1 = acc[mi][nj][1];
            float v2 = acc[mi][nj][2], v3 = acc[mi][nj][3];
            if (BIAS) {
                float bb0 = bias[col], bb1 = bias[col + 1];
                v0 += bb0; v1 += bb1; v2 += bb0; v3 += bb1;
            }
            if (RELU) {
                v0 = fmaxf(v0, 0.0f); v1 = fmaxf(v1, 0.0f);
                v2 = fmaxf(v2, 0.0f); v3 = fmaxf(v3, 0.0f);
            }
            *(float2*)(C + (size_t)row0 * N + col) = make_float2(v0, v1);
            *(float2*)(C + (size_t)row1 * N + col) = make_float2(v2, v3);
        }
    }
}

// ---------------- block reduction helpers ----------------
__device__ __forceinline__ float block_reduce_max(float v) {
    __shared__ float sh[32];
    int lane = threadIdx.x & 31, w = threadIdx.x >> 5;
#pragma unroll
    for (int o = 16; o > 0; o >>= 1) v = fmaxf(v, __shfl_xor_sync(0xffffffffu, v, o));
    if (lane == 0) sh[w] = v;
    __syncthreads();
    if (threadIdx.x < 32) {
        float t = (lane < (int)(blockDim.x >> 5)) ? sh[lane] : -INFINITY;
#pragma unroll
        for (int o = 16; o > 0; o >>= 1) t = fmaxf(t, __shfl_xor_sync(0xffffffffu, t, o));
        if (lane == 0) sh[0] = t;
    }
    __syncthreads();
    float r = sh[0];
    __syncthreads();
    return r;
}

__device__ __forceinline__ float2 block_reduce_sum2(float a, float b) {
    __shared__ float sha[32], shb[32];
    int lane = threadIdx.x & 31, w = threadIdx.x >> 5;
#pragma unroll
    for (int o = 16; o > 0; o >>= 1) {
        a += __shfl_xor_sync(0xffffffffu, a, o);
        b += __shfl_xor_sync(0xffffffffu, b, o);
    }
    if (lane == 0) { sha[w] = a; shb[w] = b; }
    __syncthreads();
    if (threadIdx.x < 32) {
        int nw = (int)(blockDim.x >> 5);
        float ta = (lane < nw) ? sha[lane] : 0.0f;
        float tb = (lane < nw) ? shb[lane] : 0.0f;
#pragma unroll
        for (int o = 16; o > 0; o >>= 1) {
            ta += __shfl_xor_sync(0xffffffffu, ta, o);
            tb += __shfl_xor_sync(0xffffffffu, tb, o);
        }
        if (lane == 0) { sha[0] = ta; shb[0] = tb; }
    }
    __syncthreads();
    float2 r = make_float2(sha[0], shb[0]);
    __syncthreads();
    return r;
}

// ---------------- softmax over rows of length NN (in place) ----------------
__global__ __launch_bounds__(256) void softmax_rows(float* __restrict__ S) {
    const int row = blockIdx.x;
    float* p = S + (size_t)row * NN;
    const int tid = threadIdx.x;
    const int PER = NN / 256;   // 16
    float vals[PER];
    float mx = -INFINITY;
#pragma unroll
    for (int i = 0; i < PER; i++) {
        vals[i] = p[tid + i * 256];
        mx = fmaxf(mx, vals[i]);
    }
    mx = block_reduce_max(mx);
    float s = 0.0f;
#pragma unroll
    for (int i = 0; i < PER; i++) {
        vals[i] = __expf(vals[i] - mx);
        s += vals[i];
    }
    float2 r = block_reduce_sum2(s, 0.0f);
    float inv = 1.0f / r.x;
#pragma unroll
    for (int i = 0; i < PER; i++) p[tid + i * 256] = vals[i] * inv;
}

// ---------------- out = LayerNorm(x + res) * g + b  (rows of DD) ----------
__global__ __launch_bounds__(256) void add_layernorm(const float* __restrict__ x,
                                                     const float* __restrict__ res,
                                                     const float* __restrict__ gamma,
                                                     const float* __restrict__ beta,
                                                     float* __restrict__ out) {
    const int row = blockIdx.x;
    const int tid = threadIdx.x;
    const int PER = DD / 256;   // 4
    float vals[PER];
    float s = 0.0f, s2 = 0.0f;
#pragma unroll
    for (int i = 0; i < PER; i++) {
        int c = tid + i * 256;
        float v = x[(size_t)row * DD + c] + res[(size_t)row * DD + c];
        vals[i] = v;
        s += v;
        s2 += v * v;
    }
    float2 r = block_reduce_sum2(s, s2);
    float mu = r.x * (1.0f / DD);
    float var = r.y * (1.0f / DD) - mu * mu;
    float rstd = rsqrtf(var + 1e-5f);
#pragma unroll
    for (int i = 0; i < PER; i++) {
        int c = tid + i * 256;
        out[(size_t)row * DD + c] = (vals[i] - mu) * rstd * gamma[c] + beta[c];
    }
}

// ---------------- launch ----------------
extern "C" void kernel_launch(void* const* d_in, const int* in_sizes, int n_in,
                              void* d_out, int out_size) {
    const float* x   = (const float*)d_in[0];
    const float* Wq  = (const float*)d_in[1];
    const float* Wk  = (const float*)d_in[2];
    const float* Wv  = (const float*)d_in[3];
    const float* Wo  = (const float*)d_in[4];
    const float* W1  = (const float*)d_in[5];
    const float* b1  = (const float*)d_in[6];
    const float* W2  = (const float*)d_in[7];
    const float* b2  = (const float*)d_in[8];
    const float* g1  = (const float*)d_in[9];
    const float* be1 = (const float*)d_in[10];
    const float* g2  = (const float*)d_in[11];
    const float* be2 = (const float*)d_in[12];
    float* out = (float*)d_out;

    float *q, *k, *v, *s, *t, *h;
    cudaGetSymbolAddress((void**)&q, g_q);
    cudaGetSymbolAddress((void**)&k, g_k);
    cudaGetSymbolAddress((void**)&v, g_v);
    cudaGetSymbolAddress((void**)&s, g_s);
    cudaGetSymbolAddress((void**)&t, g_t);
    cudaGetSymbolAddress((void**)&h, g_h);
    float* av  = q;   // reuse q for scores@v
    float* ff1 = k;   // reuse k for relu(h@W1+b1)

    dim3 blk(256);
    dim3 grid_NH(HH / 128, NN / 128);   // 32 x 32
    dim3 grid_NNg(NN / 128, NN / 128);  // 32 x 32
    dim3 grid_ND(DD / 128, NN / 128);   // 8 x 32

    // q, k, v projections: [N,D]@[D,H]
    tgemm<false, false, false><<<grid_NH, blk>>>(x, Wq, nullptr, q, NN, HH, DD);
    tgemm<false, false, false><<<grid_NH, blk>>>(x, Wk, nullptr, k, NN, HH, DD);
    tgemm<false, false, false><<<grid_NH, blk>>>(x, Wv, nullptr, v, NN, HH, DD);

    // scores = q @ k^T : [N,H]@[N,H]^T
    tgemm<true, false, false><<<grid_NNg, blk>>>(q, k, nullptr, s, NN, NN, HH);
    softmax_rows<<<NN, blk>>>(s);

    // av = scores @ v : [N,N]@[N,H]
    tgemm<false, false, false><<<grid_NH, blk>>>(s, v, nullptr, av, NN, HH, NN);

    // attn = av @ Wo : [N,H]@[H,D]
    tgemm<false, false, false><<<grid_ND, blk>>>(av, Wo, nullptr, t, NN, DD, HH);

    // h = LN(x + attn)
    add_layernorm<<<NN, blk>>>(x, t, g1, be1, h);

    // ff1 = relu(h @ W1 + b1) : [N,D]@[D,H]
    tgemm<false, true, true><<<grid_NH, blk>>>(h, W1, b1, ff1, NN, HH, DD);

    // ff2 = ff1 @ W2 + b2 : [N,H]@[H,D]
    tgemm<false, true, false><<<grid_ND, blk>>>(ff1, W2, b2, t, NN, DD, HH);

    // out = LN(h + ff2)
    add_layernorm<<<NN, blk>>>(h, t, g2, be2, out);
}